// round 13
// baseline (speedup 1.0000x reference)
#include <cstdint>
#include <cuda_runtime.h>
#include <cuda_bf16.h>
#include <mma.h>
#include <math.h>

using namespace nvcuda;

// Shapes (fixed): B=16, T=128, L=64, D=768
#define BB 16
#define TT 128
#define LL 64
#define DD 768
#define TG 4
#define NKV (BB * LL * DD)   // 786432
#define NW  (DD * DD)        // 589824

__device__ float g_ktil [NKV];
__device__ float g_vfull[NKV];
__device__ float g_c    [BB * LL];
__device__ float g_u    [DD];
__device__ float g_w    [DD];

__device__ __nv_bfloat16 g_keyh[NKV], g_keyl[NKV];
__device__ __nv_bfloat16 g_valh[NKV], g_vall[NKV];
__device__ __nv_bfloat16 g_wvh [NW],  g_wvl [NW];
__device__ __nv_bfloat16 g_wqh [NW],  g_wql [NW];   // straight split of Wq (k-major)
__device__ __nv_bfloat16 g_wkh [NW],  g_wkl [NW];   // straight split of Wk (k-major)
__device__ __nv_bfloat16 g_Gh  [NW],  g_Gl  [NW];   // G[e][f] = sum_d Wq[d][e] Wk[d][f]

// ===========================================================================
// helpers
// ===========================================================================
__device__ __forceinline__ void split8(const float* src,
                                       __nv_bfloat16* hi, __nv_bfloat16* lo)
{
    float4 a = *(const float4*)(src);
    float4 b = *(const float4*)(src + 4);
    float v[8] = {a.x, a.y, a.z, a.w, b.x, b.y, b.z, b.w};
    __nv_bfloat16 h[8], l[8];
    #pragma unroll
    for (int i = 0; i < 8; i++) {
        h[i] = __float2bfloat16(v[i]);
        l[i] = __float2bfloat16(v[i] - __bfloat162float(h[i]));
    }
    *(uint4*)hi = *(uint4*)h;
    *(uint4*)lo = *(uint4*)l;
}

__device__ __forceinline__ uint32_t s2u(const void* p) {
    uint32_t a;
    asm("{ .reg .u64 t; cvta.to.shared.u64 t, %1; cvt.u32.u64 %0, t; }"
        : "=r"(a) : "l"(p));
    return a;
}

__device__ __forceinline__ void cp_async16(uint32_t dst, const void* src) {
    asm volatile("cp.async.cg.shared.global [%0], [%1], 16;\n" :: "r"(dst), "l"(src) : "memory");
}

// ===========================================================================
// prep: straight splits (key, value, Wv, Wq, Wk) + matvecs u, w. grid 1638.
// ===========================================================================
__global__ void __launch_bounds__(256) prep_kernel(
    const float* __restrict__ key, const float* __restrict__ value,
    const float* __restrict__ Wq, const float* __restrict__ Wk,
    const float* __restrict__ Wv, const float* __restrict__ bq,
    const float* __restrict__ bk)
{
    int x = blockIdx.x;
    if (x < 1632) {
        const float* src; __nv_bfloat16 *hi, *lo; int base;
        if (x < 384)       { src = key;   hi = g_keyh; lo = g_keyl; base = x; }
        else if (x < 768)  { src = value; hi = g_valh; lo = g_vall; base = x - 384; }
        else if (x < 1056) { src = Wv;    hi = g_wvh;  lo = g_wvl;  base = x - 768; }
        else if (x < 1344) { src = Wq;    hi = g_wqh;  lo = g_wql;  base = x - 1056; }
        else               { src = Wk;    hi = g_wkh;  lo = g_wkl;  base = x - 1344; }
        int idx = (base * 256 + threadIdx.x) * 8;
        split8(src + idx, hi + idx, lo + idx);
        return;
    }
    {
        int i = x - 1632;                     // 0..5
        int e = (i % 3) * 256 + threadIdx.x;
        const float* W  = (i >= 3) ? Wk : Wq;
        const float* bb = (i >= 3) ? bq : bk;
        float acc = 0.f;
        for (int d = 0; d < DD; d++) acc += W[(size_t)d * DD + e] * bb[d];
        ((i >= 3) ? g_w : g_u)[e] = acc;
    }
}

// ===========================================================================
// NT GEMM core (R10, frozen)
// ===========================================================================
#define GSM_AH 0
#define GSM_AL 10240
#define GSM_BH 20480
#define GSM_BL 30720
#define GSM_BT 40960
#define GSM_TOTAL 45056

__device__ __forceinline__ void wgemm_nt(
    const __nv_bfloat16* __restrict__ Ah, const __nv_bfloat16* __restrict__ Al,
    const __nv_bfloat16* __restrict__ Bh, const __nv_bfloat16* __restrict__ Bl,
    const float* __restrict__ bias, float* __restrict__ C,
    int row0, int col0)
{
    extern __shared__ char dsm[];
    __nv_bfloat16* sAh = (__nv_bfloat16*)(dsm + GSM_AH);
    __nv_bfloat16* sAl = (__nv_bfloat16*)(dsm + GSM_AL);
    __nv_bfloat16* sBh = (__nv_bfloat16*)(dsm + GSM_BH);
    __nv_bfloat16* sBl = (__nv_bfloat16*)(dsm + GSM_BL);
    float* biasTile    = (float*)(dsm + GSM_BT);

    const uint32_t sbase = s2u(dsm);

    const int tid  = threadIdx.x;
    const int warp = tid >> 5;
    const int wr   = (warp >> 1) * 32;
    const int wc   = (warp & 1) * 32;

    for (int idx = tid; idx < 1024; idx += 128) {
        int col = idx & 63;
        biasTile[idx] = bias ? bias[col0 + col] : 0.f;
    }
    __syncthreads();

    wmma::fragment<wmma::accumulator, 16, 16, 16, float> c[2][2];
    #pragma unroll
    for (int i = 0; i < 2; i++)
        #pragma unroll
        for (int j = 0; j < 2; j++)
            wmma::load_matrix_sync(c[i][j], &biasTile[wc + 16 * j], 64,
                                   wmma::mem_row_major);

    const int ar = tid >> 1;
    const int as = (tid & 1) * 32;

    const __nv_bfloat16* pAh0 = Ah + (size_t)(row0 + ar) * DD + (as >> 1);
    const __nv_bfloat16* pAl0 = Al + (size_t)(row0 + ar) * DD + (as >> 1);
    const __nv_bfloat16* pBh0 = Bh + (size_t)(col0 + ar) * DD + (as >> 1);
    const __nv_bfloat16* pBl0 = Bl + (size_t)(col0 + ar) * DD + (as >> 1);

    #define ISSUE(st) do {                                                   \
        if ((st) < 24) {                                                     \
            int _buf = (st) & 1, _k0 = (st) * 32;                            \
            uint32_t d = (uint32_t)(_buf * 5120 + ar * 80 + as);             \
            cp_async16(sbase + GSM_AH + d,      pAh0 + _k0);                 \
            cp_async16(sbase + GSM_AH + d + 16, pAh0 + _k0 + 8);             \
            cp_async16(sbase + GSM_AL + d,      pAl0 + _k0);                 \
            cp_async16(sbase + GSM_AL + d + 16, pAl0 + _k0 + 8);             \
            cp_async16(sbase + GSM_BH + d,      pBh0 + _k0);                 \
            cp_async16(sbase + GSM_BH + d + 16, pBh0 + _k0 + 8);             \
            cp_async16(sbase + GSM_BL + d,      pBl0 + _k0);                 \
            cp_async16(sbase + GSM_BL + d + 16, pBl0 + _k0 + 8);             \
        }                                                                    \
        asm volatile("cp.async.commit_group;\n" ::: "memory");               \
    } while (0)

    ISSUE(0);
    ISSUE(1);

    for (int st = 0; st < 24; st++) {
        asm volatile("cp.async.wait_group 1;\n" ::: "memory");
        __syncthreads();
        const int buf = st & 1;
        const __nv_bfloat16* bAh = sAh + buf * 2560;
        const __nv_bfloat16* bAl = sAl + buf * 2560;
        const __nv_bfloat16* bBh = sBh + buf * 2560;
        const __nv_bfloat16* bBl = sBl + buf * 2560;

        #pragma unroll
        for (int ks = 0; ks < 2; ks++) {
            wmma::fragment<wmma::matrix_a, 16, 16, 16, __nv_bfloat16, wmma::row_major> ah[2], al[2];
            wmma::fragment<wmma::matrix_b, 16, 16, 16, __nv_bfloat16, wmma::col_major> bh[2], bl[2];
            #pragma unroll
            for (int i = 0; i < 2; i++) {
                wmma::load_matrix_sync(ah[i], bAh + (wr + 16 * i) * 40 + ks * 16, 40);
                wmma::load_matrix_sync(al[i], bAl + (wr + 16 * i) * 40 + ks * 16, 40);
            }
            #pragma unroll
            for (int j = 0; j < 2; j++) {
                wmma::load_matrix_sync(bh[j], bBh + (wc + 16 * j) * 40 + ks * 16, 40);
                wmma::load_matrix_sync(bl[j], bBl + (wc + 16 * j) * 40 + ks * 16, 40);
            }
            #pragma unroll
            for (int i = 0; i < 2; i++)
                #pragma unroll
                for (int j = 0; j < 2; j++) {
                    wmma::mma_sync(c[i][j], ah[i], bh[j], c[i][j]);
                    wmma::mma_sync(c[i][j], ah[i], bl[j], c[i][j]);
                    wmma::mma_sync(c[i][j], al[i], bh[j], c[i][j]);
                }
        }
        __syncthreads();
        ISSUE(st + 2);
    }
    #undef ISSUE

    #pragma unroll
    for (int i = 0; i < 2; i++)
        #pragma unroll
        for (int j = 0; j < 2; j++)
            wmma::store_matrix_sync(
                C + (size_t)(row0 + wr + 16 * i) * DD + col0 + wc + 16 * j,
                c[i][j], DD, wmma::mem_row_major);
}

// ===========================================================================
// TN GEMM for G (R12, frozen): G[e,f] = sum_d Wq[d,e]*Wk[d,f], split epilogue.
// ===========================================================================
#define TN_MS 9216
#define TN_BS 4608

__device__ __forceinline__ void wgemm_tn_G(int e0, int f0)
{
    extern __shared__ char dsm[];
    const uint32_t sbase = s2u(dsm);

    const int tid  = threadIdx.x;
    const int warp = tid >> 5;
    const int wr   = (warp >> 1) * 32;
    const int wc   = (warp & 1) * 32;

    wmma::fragment<wmma::accumulator, 16, 16, 16, float> c[2][2];
    #pragma unroll
    for (int i = 0; i < 2; i++)
        #pragma unroll
        for (int j = 0; j < 2; j++)
            wmma::fill_fragment(c[i][j], 0.f);

    const int m = tid >> 5;
    const int r = tid & 31;
    const __nv_bfloat16* p0;
    switch (m) {
        case 0:  p0 = g_wqh + (size_t)r * DD + e0; break;
        case 1:  p0 = g_wql + (size_t)r * DD + e0; break;
        case 2:  p0 = g_wkh + (size_t)r * DD + f0; break;
        default: p0 = g_wkl + (size_t)r * DD + f0; break;
    }
    const uint32_t d0 = sbase + (uint32_t)(m * TN_MS + r * 144);

    #define TISSUE(st) do {                                                  \
        if ((st) < 24) {                                                     \
            const __nv_bfloat16* _p = p0 + (size_t)(st) * 32 * DD;           \
            uint32_t d = d0 + ((st) & 1) * TN_BS;                            \
            cp_async16(d,       _p);                                         \
            cp_async16(d + 16,  _p + 8);                                     \
            cp_async16(d + 32,  _p + 16);                                    \
            cp_async16(d + 48,  _p + 24);                                    \
            cp_async16(d + 64,  _p + 32);                                    \
            cp_async16(d + 80,  _p + 40);                                    \
            cp_async16(d + 96,  _p + 48);                                    \
            cp_async16(d + 112, _p + 56);                                    \
        }                                                                    \
        asm volatile("cp.async.commit_group;\n" ::: "memory");               \
    } while (0)

    TISSUE(0);
    TISSUE(1);

    for (int st = 0; st < 24; st++) {
        asm volatile("cp.async.wait_group 1;\n" ::: "memory");
        __syncthreads();
        const int buf = st & 1;
        const __nv_bfloat16* tAh = (const __nv_bfloat16*)(dsm + 0 * TN_MS + buf * TN_BS);
        const __nv_bfloat16* tAl = (const __nv_bfloat16*)(dsm + 1 * TN_MS + buf * TN_BS);
        const __nv_bfloat16* tBh = (const __nv_bfloat16*)(dsm + 2 * TN_MS + buf * TN_BS);
        const __nv_bfloat16* tBl = (const __nv_bfloat16*)(dsm + 3 * TN_MS + buf * TN_BS);

        #pragma unroll
        for (int ks = 0; ks < 2; ks++) {
            wmma::fragment<wmma::matrix_a, 16, 16, 16, __nv_bfloat16, wmma::col_major> ah[2], al[2];
            wmma::fragment<wmma::matrix_b, 16, 16, 16, __nv_bfloat16, wmma::row_major> bh[2], bl[2];
            #pragma unroll
            for (int i = 0; i < 2; i++) {
                wmma::load_matrix_sync(ah[i], tAh + ks * 16 * 72 + wr + 16 * i, 72);
                wmma::load_matrix_sync(al[i], tAl + ks * 16 * 72 + wr + 16 * i, 72);
            }
            #pragma unroll
            for (int j = 0; j < 2; j++) {
                wmma::load_matrix_sync(bh[j], tBh + ks * 16 * 72 + wc + 16 * j, 72);
                wmma::load_matrix_sync(bl[j], tBl + ks * 16 * 72 + wc + 16 * j, 72);
            }
            #pragma unroll
            for (int i = 0; i < 2; i++)
                #pragma unroll
                for (int j = 0; j < 2; j++) {
                    wmma::mma_sync(c[i][j], ah[i], bh[j], c[i][j]);
                    wmma::mma_sync(c[i][j], ah[i], bl[j], c[i][j]);
                    wmma::mma_sync(c[i][j], al[i], bh[j], c[i][j]);
                }
        }
        __syncthreads();
        TISSUE(st + 2);
    }
    #undef TISSUE

    float* scratch = (float*)dsm;
    #pragma unroll
    for (int i = 0; i < 2; i++)
        #pragma unroll
        for (int j = 0; j < 2; j++)
            wmma::store_matrix_sync(scratch + (wr + 16 * i) * 64 + wc + 16 * j,
                                    c[i][j], 64, wmma::mem_row_major);
    __syncthreads();

    #pragma unroll
    for (int g = 0; g < 4; g++) {
        int idx = g * 1024 + tid * 8;
        int row = idx >> 6, col = idx & 63;
        __nv_bfloat16 h8[8], l8[8];
        split8(scratch + idx, h8, l8);
        size_t off = (size_t)(e0 + row) * DD + f0 + col;
        *(uint4*)(g_Gh + off) = *(uint4*)h8;
        *(uint4*)(g_Gl + off) = *(uint4*)l8;
    }
}

// ===========================================================================
// wg_L1: x<144 -> G TN tiles; x<336 -> vfull NT; x>=336 -> ckey (128 blocks)
// ===========================================================================
__global__ void __launch_bounds__(128) wg_L1(
    const float* __restrict__ key, const float* __restrict__ bq,
    const float* __restrict__ bk, const float* __restrict__ bv)
{
    int x = blockIdx.x;
    if (x < 144) {
        wgemm_tn_G((x / 12) * 64, (x % 12) * 64);
    } else if (x < 336) {
        int y = x - 144;
        wgemm_nt(g_valh, g_vall, g_wvh, g_wvl, bv, g_vfull,
                 (y / 12) * 64, (y % 12) * 64);
    } else {
        int row  = (x - 336) * 8 + (threadIdx.x >> 5) * 2;
        int lane = threadIdx.x & 31;
        #pragma unroll
        for (int rr = 0; rr < 2; rr++) {
            const float* r = key + (size_t)(row + rr) * DD;
            float acc = 0.f, s0 = 0.f;
            #pragma unroll
            for (int j = 0; j < DD / 32; j++) {
                acc += r[lane + 32 * j] * g_w[lane + 32 * j];
                s0  += bq[lane + 32 * j] * bk[lane + 32 * j];
            }
            #pragma unroll
            for (int o = 16; o; o >>= 1) {
                acc += __shfl_xor_sync(0xffffffffu, acc, o);
                s0  += __shfl_xor_sync(0xffffffffu, s0, o);
            }
            if (lane == 0) g_c[row + rr] = acc + s0;
        }
    }
}

// wg_L2: ktil = key @ G^T + u  (1024x768), 192 blocks
__global__ void __launch_bounds__(128) wg_L2()
{
    int x = blockIdx.x;
    wgemm_nt(g_keyh, g_keyl, g_Gh, g_Gl, g_u, g_ktil,
             (x / 12) * 64, (x % 12) * 64);
}

// ===========================================================================
// Fused attention: TG=4, D-chunk 256 floats (3 sub-chunks per label group),
// stage 32KB x2 = 64KB -> 3 blocks/SM. Same cp.async + k-prefetch pipeline.
// ===========================================================================
#define DCH 256
#define NSUB 3                               // 768/256
#define NCH 24                               // 8 label groups x 3
#define STAGE_FLOATS (TG * 8 * DCH)          // 8192 floats = 32768 B
#define STAGE_BYTES  (STAGE_FLOATS * 4)

__global__ void __launch_bounds__(256) attn_kernel(const float* __restrict__ query,
                                                   float* __restrict__ out)
{
    extern __shared__ float sq[];            // 2 * STAGE_FLOATS
    __shared__ float s_sc[TG][LL];
    __shared__ float s_attn[TG][LL];

    const int t0   = blockIdx.x * TG;
    const int b    = blockIdx.y;
    const int tid  = threadIdx.x;
    const int wid  = tid >> 5;
    const int lane = tid & 31;

    const float rs = 0.03608439182435161f;  // 1/sqrt(768)

    const uint32_t smq = (uint32_t)__cvta_generic_to_shared(sq);

    // cp.async mapping: chunk = 32 rows x 64 float4; 256 thr -> 8 float4 each
    const int tt_w  = tid >> 3;              // row 0..31
    const int cw_tt = tt_w >> 3;             // t in group
    const int cw_w  = tt_w & 7;              // label in group of 8
    const int colb  = tid & 7;

    const float4* kb = (const float4*)g_ktil + (size_t)b * LL * (DD / 4);
    const size_t qrow0 = ((size_t)(b * TT + t0 + cw_tt) * LL + cw_w) * DD;

    float acc[TG];
    #pragma unroll
    for (int tt = 0; tt < TG; tt++) acc[tt] = 0.f;

    // ---- issue chunk 0 (lg=0, h=0) into buffer 0 ----
    {
        const float* src = query + qrow0;
        uint32_t dst = smq + (uint32_t)(tt_w * 64) * 16;
        #pragma unroll
        for (int j = 0; j < 8; j++) {
            int c4 = colb + 8 * j;
            cp_async16(dst + c4 * 16, src + c4 * 4);
        }
        asm volatile("cp.async.commit_group;\n" ::: "memory");
    }

    // ---- preload k for chunk 0 ----
    float4 k0, k1;
    {
        const float4* krow = kb + (size_t)wid * 192;   // lg=0, h=0, l=wid
        k0 = krow[lane]; k1 = krow[lane + 32];
    }

    int lg = 0, h = 0;
    for (int c = 0; c < NCH; c++) {
        float4 n0, n1;
        if (c + 1 < NCH) {
            int hn = h + 1, lgn = lg;
            if (hn == NSUB) { hn = 0; lgn = lg + 1; }
            const float* src = query + qrow0 + (size_t)(lgn * 8) * DD + hn * DCH;
            uint32_t dst = smq + (uint32_t)(((c + 1) & 1) * STAGE_BYTES)
                               + (uint32_t)(tt_w * 64) * 16;
            #pragma unroll
            for (int j = 0; j < 8; j++) {
                int c4 = colb + 8 * j;
                cp_async16(dst + c4 * 16, src + c4 * 4);
            }
            asm volatile("cp.async.commit_group;\n" ::: "memory");
            const float4* krow = kb + (size_t)(lgn * 8 + wid) * 192 + hn * 64;
            n0 = krow[lane]; n1 = krow[lane + 32];
            asm volatile("cp.async.wait_group 1;\n" ::: "memory");
        } else {
            asm volatile("cp.async.wait_group 0;\n" ::: "memory");
        }
        __syncthreads();

        // compute buffer c&1: label l = lg*8 + wid, D slice [h*256, h*256+256)
        const int l = lg * 8 + wid;
        const float4* sqf = (const float4*)(sq + (c & 1) * STAGE_FLOATS);

        #pragma unroll
        for (int tt = 0; tt < TG; tt++) {
            const float4* qs = sqf + (tt * 8 + wid) * 64;
            float4 q0 = qs[lane], q1 = qs[lane + 32];
            acc[tt] += q0.x * k0.x + q0.y * k0.y + q0.z * k0.z + q0.w * k0.w
                     + q1.x * k1.x + q1.y * k1.y + q1.z * k1.z + q1.w * k1.w;
        }

        if (h == NSUB - 1) {
            #pragma unroll
            for (int tt = 0; tt < TG; tt++) {
                float r = acc[tt];
                #pragma unroll
                for (int o = 16; o; o >>= 1) r += __shfl_xor_sync(0xffffffffu, r, o);
                if (lane == 0) s_sc[tt][l] = (r + g_c[b * LL + l]) * rs;
                acc[tt] = 0.f;
            }
            h = 0; lg++;
        } else {
            h++;
        }
        __syncthreads();

        k0 = n0; k1 = n1;
    }

    // ---- softmax (warps 0..TG-1, one t each) ----
    if (wid < TG) {
        float v0 = s_sc[wid][lane], v1 = s_sc[wid][lane + 32];
        float m = fmaxf(v0, v1);
        #pragma unroll
        for (int o = 16; o; o >>= 1) m = fmaxf(m, __shfl_xor_sync(0xffffffffu, m, o));
        float e0 = expf(v0 - m), e1 = expf(v1 - m);
        float s = e0 + e1;
        #pragma unroll
        for (int o = 16; o; o >>= 1) s += __shfl_xor_sync(0xffffffffu, s, o);
        float inv = 1.f / s;
        s_attn[wid][lane]      = e0 * inv;
        s_attn[wid][lane + 32] = e1 * inv;
    }
    __syncthreads();

    // ---- output: read each v row once, write TG scaled rows ----
    const float4* vb = (const float4*)g_vfull + (size_t)b * LL * 192;
    #pragma unroll 1
    for (int l = wid; l < LL; l += 8) {
        const float4* vr = vb + (size_t)l * 192;
        float4 v0 = vr[lane], v1 = vr[lane + 32], v2 = vr[lane + 64],
               v3 = vr[lane + 96], v4 = vr[lane + 128], v5 = vr[lane + 160];
        #pragma unroll
        for (int tt = 0; tt < TG; tt++) {
            const float a = s_attn[tt][l];
            float4* orow = (float4*)out + ((size_t)(b * TT + t0 + tt) * LL + l) * 192;
            orow[lane]       = make_float4(a * v0.x, a * v0.y, a * v0.z, a * v0.w);
            orow[lane + 32]  = make_float4(a * v1.x, a * v1.y, a * v1.z, a * v1.w);
            orow[lane + 64]  = make_float4(a * v2.x, a * v2.y, a * v2.z, a * v2.w);
            orow[lane + 96]  = make_float4(a * v3.x, a * v3.y, a * v3.z, a * v3.w);
            orow[lane + 128] = make_float4(a * v4.x, a * v4.y, a * v4.z, a * v4.w);
            orow[lane + 160] = make_float4(a * v5.x, a * v5.y, a * v5.z, a * v5.w);
        }
    }
}

// ---------------------------------------------------------------------------
extern "C" void kernel_launch(void* const* d_in, const int* in_sizes, int n_in,
                              void* d_out, int out_size)
{
    const float* query = (const float*)d_in[0];
    const float* key   = (const float*)d_in[1];
    const float* value = (const float*)d_in[2];
    const float* Wq    = (const float*)d_in[3];
    const float* bq    = (const float*)d_in[4];
    const float* Wk    = (const float*)d_in[5];
    const float* bk    = (const float*)d_in[6];
    const float* Wv    = (const float*)d_in[7];
    const float* bv    = (const float*)d_in[8];
    float* out = (float*)d_out;

    static int attr_set = 0;
    if (!attr_set) {
        cudaFuncSetAttribute(attn_kernel, cudaFuncAttributeMaxDynamicSharedMemorySize,
                             2 * STAGE_BYTES);
        cudaFuncSetAttribute(wg_L1, cudaFuncAttributeMaxDynamicSharedMemorySize,
                             GSM_TOTAL);
        cudaFuncSetAttribute(wg_L2, cudaFuncAttributeMaxDynamicSharedMemorySize,
                             GSM_TOTAL);
        attr_set = 1;
    }

    prep_kernel<<<1638, 256>>>(key, value, Wq, Wk, Wv, bq, bk);
    wg_L1<<<464, 128, GSM_TOTAL>>>(key, bq, bk, bv);
    wg_L2<<<192, 128, GSM_TOTAL>>>();
    attn_kernel<<<dim3(TT / TG, BB), 256, 2 * STAGE_BYTES>>>(query, out);
}

// round 14
// speedup vs baseline: 1.1076x; 1.1076x over previous
#include <cstdint>
#include <cuda_runtime.h>
#include <cuda_bf16.h>
#include <mma.h>
#include <math.h>

using namespace nvcuda;

// Shapes (fixed): B=16, T=128, L=64, D=768
#define BB 16
#define TT 128
#define LL 64
#define DD 768
#define TG 4
#define NKV (BB * LL * DD)   // 786432
#define NW  (DD * DD)        // 589824

__device__ float g_ktil [NKV];
__device__ float g_vfull[NKV];
__device__ float g_c    [BB * LL];
__device__ float g_u    [DD];
__device__ float g_w    [DD];

__device__ __nv_bfloat16 g_keyh[NKV], g_keyl[NKV];
__device__ __nv_bfloat16 g_valh[NKV], g_vall[NKV];
__device__ __nv_bfloat16 g_wvh [NW],  g_wvl [NW];
__device__ __nv_bfloat16 g_wqh [NW],  g_wql [NW];   // straight split of Wq (k-major)
__device__ __nv_bfloat16 g_wkh [NW],  g_wkl [NW];   // straight split of Wk (k-major)
__device__ __nv_bfloat16 g_Gh  [NW],  g_Gl  [NW];   // G[e][f] = sum_d Wq[d][e] Wk[d][f]

// ===========================================================================
// helpers
// ===========================================================================
__device__ __forceinline__ void split8(const float* src,
                                       __nv_bfloat16* hi, __nv_bfloat16* lo)
{
    float4 a = *(const float4*)(src);
    float4 b = *(const float4*)(src + 4);
    float v[8] = {a.x, a.y, a.z, a.w, b.x, b.y, b.z, b.w};
    __nv_bfloat16 h[8], l[8];
    #pragma unroll
    for (int i = 0; i < 8; i++) {
        h[i] = __float2bfloat16(v[i]);
        l[i] = __float2bfloat16(v[i] - __bfloat162float(h[i]));
    }
    *(uint4*)hi = *(uint4*)h;
    *(uint4*)lo = *(uint4*)l;
}

__device__ __forceinline__ uint32_t s2u(const void* p) {
    uint32_t a;
    asm("{ .reg .u64 t; cvta.to.shared.u64 t, %1; cvt.u32.u64 %0, t; }"
        : "=r"(a) : "l"(p));
    return a;
}

__device__ __forceinline__ void cp_async16(uint32_t dst, const void* src) {
    asm volatile("cp.async.cg.shared.global [%0], [%1], 16;\n" :: "r"(dst), "l"(src) : "memory");
}

// ===========================================================================
// prep: straight splits (key, value, Wv, Wq, Wk) + matvecs u, w. grid 1638.
// ===========================================================================
__global__ void __launch_bounds__(256) prep_kernel(
    const float* __restrict__ key, const float* __restrict__ value,
    const float* __restrict__ Wq, const float* __restrict__ Wk,
    const float* __restrict__ Wv, const float* __restrict__ bq,
    const float* __restrict__ bk)
{
    int x = blockIdx.x;
    if (x < 1632) {
        const float* src; __nv_bfloat16 *hi, *lo; int base;
        if (x < 384)       { src = key;   hi = g_keyh; lo = g_keyl; base = x; }
        else if (x < 768)  { src = value; hi = g_valh; lo = g_vall; base = x - 384; }
        else if (x < 1056) { src = Wv;    hi = g_wvh;  lo = g_wvl;  base = x - 768; }
        else if (x < 1344) { src = Wq;    hi = g_wqh;  lo = g_wql;  base = x - 1056; }
        else               { src = Wk;    hi = g_wkh;  lo = g_wkl;  base = x - 1344; }
        int idx = (base * 256 + threadIdx.x) * 8;
        split8(src + idx, hi + idx, lo + idx);
        return;
    }
    {
        int i = x - 1632;                     // 0..5
        int e = (i % 3) * 256 + threadIdx.x;
        const float* W  = (i >= 3) ? Wk : Wq;
        const float* bb = (i >= 3) ? bq : bk;
        float acc = 0.f;
        for (int d = 0; d < DD; d++) acc += W[(size_t)d * DD + e] * bb[d];
        ((i >= 3) ? g_w : g_u)[e] = acc;
    }
}

// ===========================================================================
// NT GEMM core (R10, frozen)
// ===========================================================================
#define GSM_AH 0
#define GSM_AL 10240
#define GSM_BH 20480
#define GSM_BL 30720
#define GSM_BT 40960
#define GSM_TOTAL 45056

__device__ __forceinline__ void wgemm_nt(
    const __nv_bfloat16* __restrict__ Ah, const __nv_bfloat16* __restrict__ Al,
    const __nv_bfloat16* __restrict__ Bh, const __nv_bfloat16* __restrict__ Bl,
    const float* __restrict__ bias, float* __restrict__ C,
    int row0, int col0)
{
    extern __shared__ char dsm[];
    __nv_bfloat16* sAh = (__nv_bfloat16*)(dsm + GSM_AH);
    __nv_bfloat16* sAl = (__nv_bfloat16*)(dsm + GSM_AL);
    __nv_bfloat16* sBh = (__nv_bfloat16*)(dsm + GSM_BH);
    __nv_bfloat16* sBl = (__nv_bfloat16*)(dsm + GSM_BL);
    float* biasTile    = (float*)(dsm + GSM_BT);

    const uint32_t sbase = s2u(dsm);

    const int tid  = threadIdx.x;
    const int warp = tid >> 5;
    const int wr   = (warp >> 1) * 32;
    const int wc   = (warp & 1) * 32;

    for (int idx = tid; idx < 1024; idx += 128) {
        int col = idx & 63;
        biasTile[idx] = bias ? bias[col0 + col] : 0.f;
    }
    __syncthreads();

    wmma::fragment<wmma::accumulator, 16, 16, 16, float> c[2][2];
    #pragma unroll
    for (int i = 0; i < 2; i++)
        #pragma unroll
        for (int j = 0; j < 2; j++)
            wmma::load_matrix_sync(c[i][j], &biasTile[wc + 16 * j], 64,
                                   wmma::mem_row_major);

    const int ar = tid >> 1;
    const int as = (tid & 1) * 32;

    const __nv_bfloat16* pAh0 = Ah + (size_t)(row0 + ar) * DD + (as >> 1);
    const __nv_bfloat16* pAl0 = Al + (size_t)(row0 + ar) * DD + (as >> 1);
    const __nv_bfloat16* pBh0 = Bh + (size_t)(col0 + ar) * DD + (as >> 1);
    const __nv_bfloat16* pBl0 = Bl + (size_t)(col0 + ar) * DD + (as >> 1);

    #define ISSUE(st) do {                                                   \
        if ((st) < 24) {                                                     \
            int _buf = (st) & 1, _k0 = (st) * 32;                            \
            uint32_t d = (uint32_t)(_buf * 5120 + ar * 80 + as);             \
            cp_async16(sbase + GSM_AH + d,      pAh0 + _k0);                 \
            cp_async16(sbase + GSM_AH + d + 16, pAh0 + _k0 + 8);             \
            cp_async16(sbase + GSM_AL + d,      pAl0 + _k0);                 \
            cp_async16(sbase + GSM_AL + d + 16, pAl0 + _k0 + 8);             \
            cp_async16(sbase + GSM_BH + d,      pBh0 + _k0);                 \
            cp_async16(sbase + GSM_BH + d + 16, pBh0 + _k0 + 8);             \
            cp_async16(sbase + GSM_BL + d,      pBl0 + _k0);                 \
            cp_async16(sbase + GSM_BL + d + 16, pBl0 + _k0 + 8);             \
        }                                                                    \
        asm volatile("cp.async.commit_group;\n" ::: "memory");               \
    } while (0)

    ISSUE(0);
    ISSUE(1);

    for (int st = 0; st < 24; st++) {
        asm volatile("cp.async.wait_group 1;\n" ::: "memory");
        __syncthreads();
        const int buf = st & 1;
        const __nv_bfloat16* bAh = sAh + buf * 2560;
        const __nv_bfloat16* bAl = sAl + buf * 2560;
        const __nv_bfloat16* bBh = sBh + buf * 2560;
        const __nv_bfloat16* bBl = sBl + buf * 2560;

        #pragma unroll
        for (int ks = 0; ks < 2; ks++) {
            wmma::fragment<wmma::matrix_a, 16, 16, 16, __nv_bfloat16, wmma::row_major> ah[2], al[2];
            wmma::fragment<wmma::matrix_b, 16, 16, 16, __nv_bfloat16, wmma::col_major> bh[2], bl[2];
            #pragma unroll
            for (int i = 0; i < 2; i++) {
                wmma::load_matrix_sync(ah[i], bAh + (wr + 16 * i) * 40 + ks * 16, 40);
                wmma::load_matrix_sync(al[i], bAl + (wr + 16 * i) * 40 + ks * 16, 40);
            }
            #pragma unroll
            for (int j = 0; j < 2; j++) {
                wmma::load_matrix_sync(bh[j], bBh + (wc + 16 * j) * 40 + ks * 16, 40);
                wmma::load_matrix_sync(bl[j], bBl + (wc + 16 * j) * 40 + ks * 16, 40);
            }
            #pragma unroll
            for (int i = 0; i < 2; i++)
                #pragma unroll
                for (int j = 0; j < 2; j++) {
                    wmma::mma_sync(c[i][j], ah[i], bh[j], c[i][j]);
                    wmma::mma_sync(c[i][j], ah[i], bl[j], c[i][j]);
                    wmma::mma_sync(c[i][j], al[i], bh[j], c[i][j]);
                }
        }
        __syncthreads();
        ISSUE(st + 2);
    }
    #undef ISSUE

    #pragma unroll
    for (int i = 0; i < 2; i++)
        #pragma unroll
        for (int j = 0; j < 2; j++)
            wmma::store_matrix_sync(
                C + (size_t)(row0 + wr + 16 * i) * DD + col0 + wc + 16 * j,
                c[i][j], DD, wmma::mem_row_major);
}

// ===========================================================================
// TN GEMM for G (R12, frozen): G[e,f] = sum_d Wq[d,e]*Wk[d,f], split epilogue.
// ===========================================================================
#define TN_MS 9216
#define TN_BS 4608

__device__ __forceinline__ void wgemm_tn_G(int e0, int f0)
{
    extern __shared__ char dsm[];
    const uint32_t sbase = s2u(dsm);

    const int tid  = threadIdx.x;
    const int warp = tid >> 5;
    const int wr   = (warp >> 1) * 32;
    const int wc   = (warp & 1) * 32;

    wmma::fragment<wmma::accumulator, 16, 16, 16, float> c[2][2];
    #pragma unroll
    for (int i = 0; i < 2; i++)
        #pragma unroll
        for (int j = 0; j < 2; j++)
            wmma::fill_fragment(c[i][j], 0.f);

    const int m = tid >> 5;
    const int r = tid & 31;
    const __nv_bfloat16* p0;
    switch (m) {
        case 0:  p0 = g_wqh + (size_t)r * DD + e0; break;
        case 1:  p0 = g_wql + (size_t)r * DD + e0; break;
        case 2:  p0 = g_wkh + (size_t)r * DD + f0; break;
        default: p0 = g_wkl + (size_t)r * DD + f0; break;
    }
    const uint32_t d0 = sbase + (uint32_t)(m * TN_MS + r * 144);

    #define TISSUE(st) do {                                                  \
        if ((st) < 24) {                                                     \
            const __nv_bfloat16* _p = p0 + (size_t)(st) * 32 * DD;           \
            uint32_t d = d0 + ((st) & 1) * TN_BS;                            \
            cp_async16(d,       _p);                                         \
            cp_async16(d + 16,  _p + 8);                                     \
            cp_async16(d + 32,  _p + 16);                                    \
            cp_async16(d + 48,  _p + 24);                                    \
            cp_async16(d + 64,  _p + 32);                                    \
            cp_async16(d + 80,  _p + 40);                                    \
            cp_async16(d + 96,  _p + 48);                                    \
            cp_async16(d + 112, _p + 56);                                    \
        }                                                                    \
        asm volatile("cp.async.commit_group;\n" ::: "memory");               \
    } while (0)

    TISSUE(0);
    TISSUE(1);

    for (int st = 0; st < 24; st++) {
        asm volatile("cp.async.wait_group 1;\n" ::: "memory");
        __syncthreads();
        const int buf = st & 1;
        const __nv_bfloat16* tAh = (const __nv_bfloat16*)(dsm + 0 * TN_MS + buf * TN_BS);
        const __nv_bfloat16* tAl = (const __nv_bfloat16*)(dsm + 1 * TN_MS + buf * TN_BS);
        const __nv_bfloat16* tBh = (const __nv_bfloat16*)(dsm + 2 * TN_MS + buf * TN_BS);
        const __nv_bfloat16* tBl = (const __nv_bfloat16*)(dsm + 3 * TN_MS + buf * TN_BS);

        #pragma unroll
        for (int ks = 0; ks < 2; ks++) {
            wmma::fragment<wmma::matrix_a, 16, 16, 16, __nv_bfloat16, wmma::col_major> ah[2], al[2];
            wmma::fragment<wmma::matrix_b, 16, 16, 16, __nv_bfloat16, wmma::row_major> bh[2], bl[2];
            #pragma unroll
            for (int i = 0; i < 2; i++) {
                wmma::load_matrix_sync(ah[i], tAh + ks * 16 * 72 + wr + 16 * i, 72);
                wmma::load_matrix_sync(al[i], tAl + ks * 16 * 72 + wr + 16 * i, 72);
            }
            #pragma unroll
            for (int j = 0; j < 2; j++) {
                wmma::load_matrix_sync(bh[j], tBh + ks * 16 * 72 + wc + 16 * j, 72);
                wmma::load_matrix_sync(bl[j], tBl + ks * 16 * 72 + wc + 16 * j, 72);
            }
            #pragma unroll
            for (int i = 0; i < 2; i++)
                #pragma unroll
                for (int j = 0; j < 2; j++) {
                    wmma::mma_sync(c[i][j], ah[i], bh[j], c[i][j]);
                    wmma::mma_sync(c[i][j], ah[i], bl[j], c[i][j]);
                    wmma::mma_sync(c[i][j], al[i], bh[j], c[i][j]);
                }
        }
        __syncthreads();
        TISSUE(st + 2);
    }
    #undef TISSUE

    float* scratch = (float*)dsm;
    #pragma unroll
    for (int i = 0; i < 2; i++)
        #pragma unroll
        for (int j = 0; j < 2; j++)
            wmma::store_matrix_sync(scratch + (wr + 16 * i) * 64 + wc + 16 * j,
                                    c[i][j], 64, wmma::mem_row_major);
    __syncthreads();

    #pragma unroll
    for (int g = 0; g < 4; g++) {
        int idx = g * 1024 + tid * 8;
        int row = idx >> 6, col = idx & 63;
        __nv_bfloat16 h8[8], l8[8];
        split8(scratch + idx, h8, l8);
        size_t off = (size_t)(e0 + row) * DD + f0 + col;
        *(uint4*)(g_Gh + off) = *(uint4*)h8;
        *(uint4*)(g_Gl + off) = *(uint4*)l8;
    }
}

// ===========================================================================
// wave A: x<144 -> G TN tiles; x>=144 -> ckey (128 blocks). grid 272.
// ===========================================================================
__global__ void __launch_bounds__(128) wg_A(
    const float* __restrict__ key, const float* __restrict__ bq,
    const float* __restrict__ bk)
{
    int x = blockIdx.x;
    if (x < 144) {
        wgemm_tn_G((x / 12) * 64, (x % 12) * 64);
    } else {
        int row  = (x - 144) * 8 + (threadIdx.x >> 5) * 2;
        int lane = threadIdx.x & 31;
        #pragma unroll
        for (int rr = 0; rr < 2; rr++) {
            const float* r = key + (size_t)(row + rr) * DD;
            float acc = 0.f, s0 = 0.f;
            #pragma unroll
            for (int j = 0; j < DD / 32; j++) {
                acc += r[lane + 32 * j] * g_w[lane + 32 * j];
                s0  += bq[lane + 32 * j] * bk[lane + 32 * j];
            }
            #pragma unroll
            for (int o = 16; o; o >>= 1) {
                acc += __shfl_xor_sync(0xffffffffu, acc, o);
                s0  += __shfl_xor_sync(0xffffffffu, s0, o);
            }
            if (lane == 0) g_c[row + rr] = acc + s0;
        }
    }
}

// ===========================================================================
// wave B: x<192 -> vfull NT; x>=192 -> ktil NT (key @ G^T + u). grid 384.
// ===========================================================================
__global__ void __launch_bounds__(128) wg_B(const float* __restrict__ bv)
{
    int x = blockIdx.x;
    if (x < 192) {
        wgemm_nt(g_valh, g_vall, g_wvh, g_wvl, bv, g_vfull,
                 (x / 12) * 64, (x % 12) * 64);
    } else {
        int y = x - 192;
        wgemm_nt(g_keyh, g_keyl, g_Gh, g_Gl, g_u, g_ktil,
                 (y / 12) * 64, (y % 12) * 64);
    }
}

// ===========================================================================
// Fused attention (R6/R12 proven config: 384-float chunks, 16 chunks,
// 2 x 49KB stages, k-prefetch overlapping the cp.async wait)
// ===========================================================================
#define STAGE_FLOATS (TG * 8 * 384)
#define STAGE_BYTES  (STAGE_FLOATS * 4)

__global__ void __launch_bounds__(256) attn_kernel(const float* __restrict__ query,
                                                   float* __restrict__ out)
{
    extern __shared__ float sq[];
    __shared__ float s_sc[TG][LL];
    __shared__ float s_attn[TG][LL];

    const int t0   = blockIdx.x * TG;
    const int b    = blockIdx.y;
    const int tid  = threadIdx.x;
    const int wid  = tid >> 5;
    const int lane = tid & 31;

    const float rs = 0.03608439182435161f;

    const uint32_t smq = (uint32_t)__cvta_generic_to_shared(sq);

    const int tt_w  = tid >> 3;
    const int cw_tt = tt_w >> 3;
    const int cw_w  = tt_w & 7;
    const int colb  = tid & 7;

    const float4* kb = (const float4*)g_ktil + (size_t)b * LL * (DD / 4);

    float acc[TG];
    #pragma unroll
    for (int tt = 0; tt < TG; tt++) acc[tt] = 0.f;

    {
        const float* src = query + ((size_t)(b * TT + t0 + cw_tt) * LL + cw_w) * DD;
        uint32_t dst = smq + (uint32_t)(tt_w * 96) * 16;
        #pragma unroll
        for (int j = 0; j < 12; j++) {
            int c4 = colb + 8 * j;
            cp_async16(dst + c4 * 16, src + c4 * 4);
        }
        asm volatile("cp.async.commit_group;\n" ::: "memory");
    }

    float4 k0, k1, k2;
    {
        const float4* krow = kb + (size_t)wid * 192;
        k0 = krow[lane]; k1 = krow[lane + 32]; k2 = krow[lane + 64];
    }

    for (int c = 0; c < 16; c++) {
        float4 n0, n1, n2;
        if (c < 15) {
            const int lg = (c + 1) >> 1, h = (c + 1) & 1;
            const float* src = query +
                ((size_t)(b * TT + t0 + cw_tt) * LL + (lg * 8 + cw_w)) * DD + h * 384;
            uint32_t dst = smq + (uint32_t)(((c + 1) & 1) * STAGE_BYTES)
                               + (uint32_t)(tt_w * 96) * 16;
            #pragma unroll
            for (int j = 0; j < 12; j++) {
                int c4 = colb + 8 * j;
                cp_async16(dst + c4 * 16, src + c4 * 4);
            }
            asm volatile("cp.async.commit_group;\n" ::: "memory");
            const float4* krow = kb + (size_t)(lg * 8 + wid) * 192 + h * 96;
            n0 = krow[lane]; n1 = krow[lane + 32]; n2 = krow[lane + 64];
            asm volatile("cp.async.wait_group 1;\n" ::: "memory");
        } else {
            asm volatile("cp.async.wait_group 0;\n" ::: "memory");
        }
        __syncthreads();

        const int lg = c >> 1, h = c & 1;
        const int l = lg * 8 + wid;
        const float4* sqf = (const float4*)(sq + (c & 1) * STAGE_FLOATS);

        #pragma unroll
        for (int tt = 0; tt < TG; tt++) {
            const float4* qs = sqf + (tt * 8 + wid) * 96;
            float4 q0 = qs[lane], q1 = qs[lane + 32], q2 = qs[lane + 64];
            acc[tt] += q0.x * k0.x + q0.y * k0.y + q0.z * k0.z + q0.w * k0.w
                     + q1.x * k1.x + q1.y * k1.y + q1.z * k1.z + q1.w * k1.w
                     + q2.x * k2.x + q2.y * k2.y + q2.z * k2.z + q2.w * k2.w;
        }

        if (h == 1) {
            #pragma unroll
            for (int tt = 0; tt < TG; tt++) {
                float r = acc[tt];
                #pragma unroll
                for (int o = 16; o; o >>= 1) r += __shfl_xor_sync(0xffffffffu, r, o);
                if (lane == 0) s_sc[tt][l] = (r + g_c[b * LL + l]) * rs;
                acc[tt] = 0.f;
            }
        }
        __syncthreads();

        k0 = n0; k1 = n1; k2 = n2;
    }

    if (wid < TG) {
        float v0 = s_sc[wid][lane], v1 = s_sc[wid][lane + 32];
        float m = fmaxf(v0, v1);
        #pragma unroll
        for (int o = 16; o; o >>= 1) m = fmaxf(m, __shfl_xor_sync(0xffffffffu, m, o));
        float e0 = expf(v0 - m), e1 = expf(v1 - m);
        float s = e0 + e1;
        #pragma unroll
        for (int o = 16; o; o >>= 1) s += __shfl_xor_sync(0xffffffffu, s, o);
        float inv = 1.f / s;
        s_attn[wid][lane]      = e0 * inv;
        s_attn[wid][lane + 32] = e1 * inv;
    }
    __syncthreads();

    const float4* vb = (const float4*)g_vfull + (size_t)b * LL * 192;
    #pragma unroll 1
    for (int l = wid; l < LL; l += 8) {
        const float4* vr = vb + (size_t)l * 192;
        float4 v0 = vr[lane], v1 = vr[lane + 32], v2 = vr[lane + 64],
               v3 = vr[lane + 96], v4 = vr[lane + 128], v5 = vr[lane + 160];
        #pragma unroll
        for (int tt = 0; tt < TG; tt++) {
            const float a = s_attn[tt][l];
            float4* orow = (float4*)out + ((size_t)(b * TT + t0 + tt) * LL + l) * 192;
            orow[lane]       = make_float4(a * v0.x, a * v0.y, a * v0.z, a * v0.w);
            orow[lane + 32]  = make_float4(a * v1.x, a * v1.y, a * v1.z, a * v1.w);
            orow[lane + 64]  = make_float4(a * v2.x, a * v2.y, a * v2.z, a * v2.w);
            orow[lane + 96]  = make_float4(a * v3.x, a * v3.y, a * v3.z, a * v3.w);
            orow[lane + 128] = make_float4(a * v4.x, a * v4.y, a * v4.z, a * v4.w);
            orow[lane + 160] = make_float4(a * v5.x, a * v5.y, a * v5.z, a * v5.w);
        }
    }
}

// ---------------------------------------------------------------------------
extern "C" void kernel_launch(void* const* d_in, const int* in_sizes, int n_in,
                              void* d_out, int out_size)
{
    const float* query = (const float*)d_in[0];
    const float* key   = (const float*)d_in[1];
    const float* value = (const float*)d_in[2];
    const float* Wq    = (const float*)d_in[3];
    const float* bq    = (const float*)d_in[4];
    const float* Wk    = (const float*)d_in[5];
    const float* bk    = (const float*)d_in[6];
    const float* Wv    = (const float*)d_in[7];
    const float* bv    = (const float*)d_in[8];
    float* out = (float*)d_out;

    static int attr_set = 0;
    if (!attr_set) {
        cudaFuncSetAttribute(attn_kernel, cudaFuncAttributeMaxDynamicSharedMemorySize,
                             2 * STAGE_BYTES);
        cudaFuncSetAttribute(wg_A, cudaFuncAttributeMaxDynamicSharedMemorySize,
                             GSM_TOTAL);
        cudaFuncSetAttribute(wg_B, cudaFuncAttributeMaxDynamicSharedMemorySize,
                             GSM_TOTAL);
        attr_set = 1;
    }

    prep_kernel<<<1638, 256>>>(key, value, Wq, Wk, Wv, bq, bk);
    wg_A<<<272, 128, GSM_TOTAL>>>(key, bq, bk);
    wg_B<<<384, 128, GSM_TOTAL>>>(bv);
    attn_kernel<<<dim3(TT / TG, BB), 256, 2 * STAGE_BYTES>>>(query, out);
}

// round 16
// speedup vs baseline: 1.1117x; 1.0037x over previous
#include <cstdint>
#include <cuda_runtime.h>
#include <cuda_bf16.h>
#include <mma.h>
#include <math.h>

using namespace nvcuda;

// Shapes (fixed): B=16, T=128, L=64, D=768
#define BB 16
#define TT 128
#define LL 64
#define DD 768
#define TG 4
#define NKV (BB * LL * DD)   // 786432
#define NW  (DD * DD)        // 589824

__device__ float g_ktil [NKV];
__device__ float g_vfull[NKV];
__device__ float g_c    [BB * LL];
__device__ float g_u    [DD];
__device__ float g_w    [DD];

__device__ __nv_bfloat16 g_keyh[NKV], g_keyl[NKV];
__device__ __nv_bfloat16 g_valh[NKV], g_vall[NKV];
__device__ __nv_bfloat16 g_wvh [NW],  g_wvl [NW];
__device__ __nv_bfloat16 g_wqh [NW],  g_wql [NW];   // straight split of Wq (k-major)
__device__ __nv_bfloat16 g_wkh [NW],  g_wkl [NW];   // straight split of Wk (k-major)
__device__ __nv_bfloat16 g_Gh  [NW],  g_Gl  [NW];   // G[e][f] = sum_d Wq[d][e] Wk[d][f]

// ===========================================================================
// helpers
// ===========================================================================
__device__ __forceinline__ void split8(const float* src,
                                       __nv_bfloat16* hi, __nv_bfloat16* lo)
{
    float4 a = *(const float4*)(src);
    float4 b = *(const float4*)(src + 4);
    float v[8] = {a.x, a.y, a.z, a.w, b.x, b.y, b.z, b.w};
    __nv_bfloat16 h[8], l[8];
    #pragma unroll
    for (int i = 0; i < 8; i++) {
        h[i] = __float2bfloat16(v[i]);
        l[i] = __float2bfloat16(v[i] - __bfloat162float(h[i]));
    }
    *(uint4*)hi = *(uint4*)h;
    *(uint4*)lo = *(uint4*)l;
}

__device__ __forceinline__ uint32_t s2u(const void* p) {
    uint32_t a;
    asm("{ .reg .u64 t; cvta.to.shared.u64 t, %1; cvt.u32.u64 %0, t; }"
        : "=r"(a) : "l"(p));
    return a;
}

__device__ __forceinline__ void cp_async16(uint32_t dst, const void* src) {
    asm volatile("cp.async.cg.shared.global [%0], [%1], 16;\n" :: "r"(dst), "l"(src) : "memory");
}

// ===========================================================================
// prep: straight splits (key, value, Wv, Wq, Wk) + matvecs u, w. grid 1638.
// ===========================================================================
__global__ void __launch_bounds__(256) prep_kernel(
    const float* __restrict__ key, const float* __restrict__ value,
    const float* __restrict__ Wq, const float* __restrict__ Wk,
    const float* __restrict__ Wv, const float* __restrict__ bq,
    const float* __restrict__ bk)
{
    int x = blockIdx.x;
    if (x < 1632) {
        const float* src; __nv_bfloat16 *hi, *lo; int base;
        if (x < 384)       { src = key;   hi = g_keyh; lo = g_keyl; base = x; }
        else if (x < 768)  { src = value; hi = g_valh; lo = g_vall; base = x - 384; }
        else if (x < 1056) { src = Wv;    hi = g_wvh;  lo = g_wvl;  base = x - 768; }
        else if (x < 1344) { src = Wq;    hi = g_wqh;  lo = g_wql;  base = x - 1056; }
        else               { src = Wk;    hi = g_wkh;  lo = g_wkl;  base = x - 1344; }
        int idx = (base * 256 + threadIdx.x) * 8;
        split8(src + idx, hi + idx, lo + idx);
        return;
    }
    {
        int i = x - 1632;                     // 0..5
        int e = (i % 3) * 256 + threadIdx.x;
        const float* W  = (i >= 3) ? Wk : Wq;
        const float* bb = (i >= 3) ? bq : bk;
        float acc = 0.f;
        for (int d = 0; d < DD; d++) acc += W[(size_t)d * DD + e] * bb[d];
        ((i >= 3) ? g_w : g_u)[e] = acc;
    }
}

// ===========================================================================
// NT GEMM core: R10 compute structure, 3-stage cp.async pipeline.
// 128 threads, 4 warps @ 32x32, BM=BN=64, BK=32.
// One buffer per matrix = 64 rows x 80B = 5120B; 3 buffers per matrix.
// smem: 4 x 15360 + bias 4096 = 65536B.
// ===========================================================================
#define GSM_AH 0
#define GSM_AL 15360
#define GSM_BH 30720
#define GSM_BL 46080
#define GSM_BT 61440
#define GSM_TOTAL 65536

__device__ __forceinline__ void wgemm_nt(
    const __nv_bfloat16* __restrict__ Ah, const __nv_bfloat16* __restrict__ Al,
    const __nv_bfloat16* __restrict__ Bh, const __nv_bfloat16* __restrict__ Bl,
    const float* __restrict__ bias, float* __restrict__ C,
    int row0, int col0)
{
    extern __shared__ char dsm[];
    __nv_bfloat16* sAh = (__nv_bfloat16*)(dsm + GSM_AH);
    __nv_bfloat16* sAl = (__nv_bfloat16*)(dsm + GSM_AL);
    __nv_bfloat16* sBh = (__nv_bfloat16*)(dsm + GSM_BH);
    __nv_bfloat16* sBl = (__nv_bfloat16*)(dsm + GSM_BL);
    float* biasTile    = (float*)(dsm + GSM_BT);

    const uint32_t sbase = s2u(dsm);

    const int tid  = threadIdx.x;
    const int warp = tid >> 5;
    const int wr   = (warp >> 1) * 32;
    const int wc   = (warp & 1) * 32;

    for (int idx = tid; idx < 1024; idx += 128) {
        int col = idx & 63;
        biasTile[idx] = bias ? bias[col0 + col] : 0.f;
    }
    __syncthreads();

    wmma::fragment<wmma::accumulator, 16, 16, 16, float> c[2][2];
    #pragma unroll
    for (int i = 0; i < 2; i++)
        #pragma unroll
        for (int j = 0; j < 2; j++)
            wmma::load_matrix_sync(c[i][j], &biasTile[wc + 16 * j], 64,
                                   wmma::mem_row_major);

    const int ar = tid >> 1;
    const int as = (tid & 1) * 32;

    const __nv_bfloat16* pAh0 = Ah + (size_t)(row0 + ar) * DD + (as >> 1);
    const __nv_bfloat16* pAl0 = Al + (size_t)(row0 + ar) * DD + (as >> 1);
    const __nv_bfloat16* pBh0 = Bh + (size_t)(col0 + ar) * DD + (as >> 1);
    const __nv_bfloat16* pBl0 = Bl + (size_t)(col0 + ar) * DD + (as >> 1);

    // buffer stride: 5120 bytes = 2560 bf16 elements
    #define ISSUE(st, bf) do {                                               \
        if ((st) < 24) {                                                     \
            int _k0 = (st) * 32;                                             \
            uint32_t d = (uint32_t)((bf) * 5120 + ar * 80 + as);             \
            cp_async16(sbase + GSM_AH + d,      pAh0 + _k0);                 \
            cp_async16(sbase + GSM_AH + d + 16, pAh0 + _k0 + 8);             \
            cp_async16(sbase + GSM_AL + d,      pAl0 + _k0);                 \
            cp_async16(sbase + GSM_AL + d + 16, pAl0 + _k0 + 8);             \
            cp_async16(sbase + GSM_BH + d,      pBh0 + _k0);                 \
            cp_async16(sbase + GSM_BH + d + 16, pBh0 + _k0 + 8);             \
            cp_async16(sbase + GSM_BL + d,      pBl0 + _k0);                 \
            cp_async16(sbase + GSM_BL + d + 16, pBl0 + _k0 + 8);             \
        }                                                                    \
        asm volatile("cp.async.commit_group;\n" ::: "memory");               \
    } while (0)

    ISSUE(0, 0);
    ISSUE(1, 1);
    ISSUE(2, 2);

    int buf = 0;
    for (int st = 0; st < 24; st++) {
        asm volatile("cp.async.wait_group 2;\n" ::: "memory");
        __syncthreads();
        const __nv_bfloat16* bAh = sAh + buf * 2560;
        const __nv_bfloat16* bAl = sAl + buf * 2560;
        const __nv_bfloat16* bBh = sBh + buf * 2560;
        const __nv_bfloat16* bBl = sBl + buf * 2560;

        #pragma unroll
        for (int ks = 0; ks < 2; ks++) {
            wmma::fragment<wmma::matrix_a, 16, 16, 16, __nv_bfloat16, wmma::row_major> ah[2], al[2];
            wmma::fragment<wmma::matrix_b, 16, 16, 16, __nv_bfloat16, wmma::col_major> bh[2], bl[2];
            #pragma unroll
            for (int i = 0; i < 2; i++) {
                wmma::load_matrix_sync(ah[i], bAh + (wr + 16 * i) * 40 + ks * 16, 40);
                wmma::load_matrix_sync(al[i], bAl + (wr + 16 * i) * 40 + ks * 16, 40);
            }
            #pragma unroll
            for (int j = 0; j < 2; j++) {
                wmma::load_matrix_sync(bh[j], bBh + (wc + 16 * j) * 40 + ks * 16, 40);
                wmma::load_matrix_sync(bl[j], bBl + (wc + 16 * j) * 40 + ks * 16, 40);
            }
            #pragma unroll
            for (int i = 0; i < 2; i++)
                #pragma unroll
                for (int j = 0; j < 2; j++) {
                    wmma::mma_sync(c[i][j], ah[i], bh[j], c[i][j]);
                    wmma::mma_sync(c[i][j], ah[i], bl[j], c[i][j]);
                    wmma::mma_sync(c[i][j], al[i], bh[j], c[i][j]);
                }
        }
        __syncthreads();
        ISSUE(st + 3, buf);
        buf = (buf == 2) ? 0 : buf + 1;
    }
    #undef ISSUE

    #pragma unroll
    for (int i = 0; i < 2; i++)
        #pragma unroll
        for (int j = 0; j < 2; j++)
            wmma::store_matrix_sync(
                C + (size_t)(row0 + wr + 16 * i) * DD + col0 + wc + 16 * j,
                c[i][j], DD, wmma::mem_row_major);
}

// ===========================================================================
// TN GEMM for G: 3-stage pipeline. Tiles [32 k][64 mn], pitch 72.
// Per-buffer 4608B (32 rows x 144B); per-matrix 3 x 4608 = 13824B.
// ===========================================================================
#define TN_MS 13824
#define TN_BS 4608
#define TN_TOTAL 55296

__device__ __forceinline__ void wgemm_tn_G(int e0, int f0)
{
    extern __shared__ char dsm[];
    const uint32_t sbase = s2u(dsm);

    const int tid  = threadIdx.x;
    const int warp = tid >> 5;
    const int wr   = (warp >> 1) * 32;
    const int wc   = (warp & 1) * 32;

    wmma::fragment<wmma::accumulator, 16, 16, 16, float> c[2][2];
    #pragma unroll
    for (int i = 0; i < 2; i++)
        #pragma unroll
        for (int j = 0; j < 2; j++)
            wmma::fill_fragment(c[i][j], 0.f);

    const int m = tid >> 5;
    const int r = tid & 31;
    const __nv_bfloat16* p0;
    switch (m) {
        case 0:  p0 = g_wqh + (size_t)r * DD + e0; break;
        case 1:  p0 = g_wql + (size_t)r * DD + e0; break;
        case 2:  p0 = g_wkh + (size_t)r * DD + f0; break;
        default: p0 = g_wkl + (size_t)r * DD + f0; break;
    }
    const uint32_t d0 = sbase + (uint32_t)(m * TN_MS + r * 144);

    #define TISSUE(st, bf) do {                                              \
        if ((st) < 24) {                                                     \
            const __nv_bfloat16* _p = p0 + (size_t)(st) * 32 * DD;           \
            uint32_t d = d0 + (bf) * TN_BS;                                  \
            cp_async16(d,       _p);                                         \
            cp_async16(d + 16,  _p + 8);                                     \
            cp_async16(d + 32,  _p + 16);                                    \
            cp_async16(d + 48,  _p + 24);                                    \
            cp_async16(d + 64,  _p + 32);                                    \
            cp_async16(d + 80,  _p + 40);                                    \
            cp_async16(d + 96,  _p + 48);                                    \
            cp_async16(d + 112, _p + 56);                                    \
        }                                                                    \
        asm volatile("cp.async.commit_group;\n" ::: "memory");               \
    } while (0)

    TISSUE(0, 0);
    TISSUE(1, 1);
    TISSUE(2, 2);

    int buf = 0;
    for (int st = 0; st < 24; st++) {
        asm volatile("cp.async.wait_group 2;\n" ::: "memory");
        __syncthreads();
        const __nv_bfloat16* tAh = (const __nv_bfloat16*)(dsm + 0 * TN_MS + buf * TN_BS);
        const __nv_bfloat16* tAl = (const __nv_bfloat16*)(dsm + 1 * TN_MS + buf * TN_BS);
        const __nv_bfloat16* tBh = (const __nv_bfloat16*)(dsm + 2 * TN_MS + buf * TN_BS);
        const __nv_bfloat16* tBl = (const __nv_bfloat16*)(dsm + 3 * TN_MS + buf * TN_BS);

        #pragma unroll
        for (int ks = 0; ks < 2; ks++) {
            wmma::fragment<wmma::matrix_a, 16, 16, 16, __nv_bfloat16, wmma::col_major> ah[2], al[2];
            wmma::fragment<wmma::matrix_b, 16, 16, 16, __nv_bfloat16, wmma::row_major> bh[2], bl[2];
            #pragma unroll
            for (int i = 0; i < 2; i++) {
                wmma::load_matrix_sync(ah[i], tAh + ks * 16 * 72 + wr + 16 * i, 72);
                wmma::load_matrix_sync(al[i], tAl + ks * 16 * 72 + wr + 16 * i, 72);
            }
            #pragma unroll
            for (int j = 0; j < 2; j++) {
                wmma::load_matrix_sync(bh[j], tBh + ks * 16 * 72 + wc + 16 * j, 72);
                wmma::load_matrix_sync(bl[j], tBl + ks * 16 * 72 + wc + 16 * j, 72);
            }
            #pragma unroll
            for (int i = 0; i < 2; i++)
                #pragma unroll
                for (int j = 0; j < 2; j++) {
                    wmma::mma_sync(c[i][j], ah[i], bh[j], c[i][j]);
                    wmma::mma_sync(c[i][j], ah[i], bl[j], c[i][j]);
                    wmma::mma_sync(c[i][j], al[i], bh[j], c[i][j]);
                }
        }
        __syncthreads();
        TISSUE(st + 3, buf);
        buf = (buf == 2) ? 0 : buf + 1;
    }
    #undef TISSUE

    float* scratch = (float*)dsm;
    #pragma unroll
    for (int i = 0; i < 2; i++)
        #pragma unroll
        for (int j = 0; j < 2; j++)
            wmma::store_matrix_sync(scratch + (wr + 16 * i) * 64 + wc + 16 * j,
                                    c[i][j], 64, wmma::mem_row_major);
    __syncthreads();

    #pragma unroll
    for (int g = 0; g < 4; g++) {
        int idx = g * 1024 + tid * 8;
        int row = idx >> 6, col = idx & 63;
        __nv_bfloat16 h8[8], l8[8];
        split8(scratch + idx, h8, l8);
        size_t off = (size_t)(e0 + row) * DD + f0 + col;
        *(uint4*)(g_Gh + off) = *(uint4*)h8;
        *(uint4*)(g_Gl + off) = *(uint4*)l8;
    }
}

// ===========================================================================
// wave A: x<144 -> G TN tiles; x>=144 -> ckey (128 blocks). grid 272.
// ===========================================================================
__global__ void __launch_bounds__(128) wg_A(
    const float* __restrict__ key, const float* __restrict__ bq,
    const float* __restrict__ bk)
{
    int x = blockIdx.x;
    if (x < 144) {
        wgemm_tn_G((x / 12) * 64, (x % 12) * 64);
    } else {
        int row  = (x - 144) * 8 + (threadIdx.x >> 5) * 2;
        int lane = threadIdx.x & 31;
        #pragma unroll
        for (int rr = 0; rr < 2; rr++) {
            const float* r = key + (size_t)(row + rr) * DD;
            float acc = 0.f, s0 = 0.f;
            #pragma unroll
            for (int j = 0; j < DD / 32; j++) {
                acc += r[lane + 32 * j] * g_w[lane + 32 * j];
                s0  += bq[lane + 32 * j] * bk[lane + 32 * j];
            }
            #pragma unroll
            for (int o = 16; o; o >>= 1) {
                acc += __shfl_xor_sync(0xffffffffu, acc, o);
                s0  += __shfl_xor_sync(0xffffffffu, s0, o);
            }
            if (lane == 0) g_c[row + rr] = acc + s0;
        }
    }
}

// ===========================================================================
// wave B: x<192 -> vfull NT; x>=192 -> ktil NT (key @ G^T + u). grid 384.
// ===========================================================================
__global__ void __launch_bounds__(128) wg_B(const float* __restrict__ bv)
{
    int x = blockIdx.x;
    if (x < 192) {
        wgemm_nt(g_valh, g_vall, g_wvh, g_wvl, bv, g_vfull,
                 (x / 12) * 64, (x % 12) * 64);
    } else {
        int y = x - 192;
        wgemm_nt(g_keyh, g_keyl, g_Gh, g_Gl, g_u, g_ktil,
                 (y / 12) * 64, (y % 12) * 64);
    }
}

// ===========================================================================
// Fused attention (frozen: 384-float chunks, 16 chunks, 2 x 49KB stages,
// k-prefetch overlapping the cp.async wait)
// ===========================================================================
#define STAGE_FLOATS (TG * 8 * 384)
#define STAGE_BYTES  (STAGE_FLOATS * 4)

__global__ void __launch_bounds__(256) attn_kernel(const float* __restrict__ query,
                                                   float* __restrict__ out)
{
    extern __shared__ float sq[];
    __shared__ float s_sc[TG][LL];
    __shared__ float s_attn[TG][LL];

    const int t0   = blockIdx.x * TG;
    const int b    = blockIdx.y;
    const int tid  = threadIdx.x;
    const int wid  = tid >> 5;
    const int lane = tid & 31;

    const float rs = 0.03608439182435161f;

    const uint32_t smq = (uint32_t)__cvta_generic_to_shared(sq);

    const int tt_w  = tid >> 3;
    const int cw_tt = tt_w >> 3;
    const int cw_w  = tt_w & 7;
    const int colb  = tid & 7;

    const float4* kb = (const float4*)g_ktil + (size_t)b * LL * (DD / 4);

    float acc[TG];
    #pragma unroll
    for (int tt = 0; tt < TG; tt++) acc[tt] = 0.f;

    {
        const float* src = query + ((size_t)(b * TT + t0 + cw_tt) * LL + cw_w) * DD;
        uint32_t dst = smq + (uint32_t)(tt_w * 96) * 16;
        #pragma unroll
        for (int j = 0; j < 12; j++) {
            int c4 = colb + 8 * j;
            cp_async16(dst + c4 * 16, src + c4 * 4);
        }
        asm volatile("cp.async.commit_group;\n" ::: "memory");
    }

    float4 k0, k1, k2;
    {
        const float4* krow = kb + (size_t)wid * 192;
        k0 = krow[lane]; k1 = krow[lane + 32]; k2 = krow[lane + 64];
    }

    for (int c = 0; c < 16; c++) {
        float4 n0, n1, n2;
        if (c < 15) {
            const int lg = (c + 1) >> 1, h = (c + 1) & 1;
            const float* src = query +
                ((size_t)(b * TT + t0 + cw_tt) * LL + (lg * 8 + cw_w)) * DD + h * 384;
            uint32_t dst = smq + (uint32_t)(((c + 1) & 1) * STAGE_BYTES)
                               + (uint32_t)(tt_w * 96) * 16;
            #pragma unroll
            for (int j = 0; j < 12; j++) {
                int c4 = colb + 8 * j;
                cp_async16(dst + c4 * 16, src + c4 * 4);
            }
            asm volatile("cp.async.commit_group;\n" ::: "memory");
            const float4* krow = kb + (size_t)(lg * 8 + wid) * 192 + h * 96;
            n0 = krow[lane]; n1 = krow[lane + 32]; n2 = krow[lane + 64];
            asm volatile("cp.async.wait_group 1;\n" ::: "memory");
        } else {
            asm volatile("cp.async.wait_group 0;\n" ::: "memory");
        }
        __syncthreads();

        const int lg = c >> 1, h = c & 1;
        const int l = lg * 8 + wid;
        const float4* sqf = (const float4*)(sq + (c & 1) * STAGE_FLOATS);

        #pragma unroll
        for (int tt = 0; tt < TG; tt++) {
            const float4* qs = sqf + (tt * 8 + wid) * 96;
            float4 q0 = qs[lane], q1 = qs[lane + 32], q2 = qs[lane + 64];
            acc[tt] += q0.x * k0.x + q0.y * k0.y + q0.z * k0.z + q0.w * k0.w
                     + q1.x * k1.x + q1.y * k1.y + q1.z * k1.z + q1.w * k1.w
                     + q2.x * k2.x + q2.y * k2.y + q2.z * k2.z + q2.w * k2.w;
        }

        if (h == 1) {
            #pragma unroll
            for (int tt = 0; tt < TG; tt++) {
                float r = acc[tt];
                #pragma unroll
                for (int o = 16; o; o >>= 1) r += __shfl_xor_sync(0xffffffffu, r, o);
                if (lane == 0) s_sc[tt][l] = (r + g_c[b * LL + l]) * rs;
                acc[tt] = 0.f;
            }
        }
        __syncthreads();

        k0 = n0; k1 = n1; k2 = n2;
    }

    if (wid < TG) {
        float v0 = s_sc[wid][lane], v1 = s_sc[wid][lane + 32];
        float m = fmaxf(v0, v1);
        #pragma unroll
        for (int o = 16; o; o >>= 1) m = fmaxf(m, __shfl_xor_sync(0xffffffffu, m, o));
        float e0 = expf(v0 - m), e1 = expf(v1 - m);
        float s = e0 + e1;
        #pragma unroll
        for (int o = 16; o; o >>= 1) s += __shfl_xor_sync(0xffffffffu, s, o);
        float inv = 1.f / s;
        s_attn[wid][lane]      = e0 * inv;
        s_attn[wid][lane + 32] = e1 * inv;
    }
    __syncthreads();

    const float4* vb = (const float4*)g_vfull + (size_t)b * LL * 192;
    #pragma unroll 1
    for (int l = wid; l < LL; l += 8) {
        const float4* vr = vb + (size_t)l * 192;
        float4 v0 = vr[lane], v1 = vr[lane + 32], v2 = vr[lane + 64],
               v3 = vr[lane + 96], v4 = vr[lane + 128], v5 = vr[lane + 160];
        #pragma unroll
        for (int tt = 0; tt < TG; tt++) {
            const float a = s_attn[tt][l];
            float4* orow = (float4*)out + ((size_t)(b * TT + t0 + tt) * LL + l) * 192;
            orow[lane]       = make_float4(a * v0.x, a * v0.y, a * v0.z, a * v0.w);
            orow[lane + 32]  = make_float4(a * v1.x, a * v1.y, a * v1.z, a * v1.w);
            orow[lane + 64]  = make_float4(a * v2.x, a * v2.y, a * v2.z, a * v2.w);
            orow[lane + 96]  = make_float4(a * v3.x, a * v3.y, a * v3.z, a * v3.w);
            orow[lane + 128] = make_float4(a * v4.x, a * v4.y, a * v4.z, a * v4.w);
            orow[lane + 160] = make_float4(a * v5.x, a * v5.y, a * v5.z, a * v5.w);
        }
    }
}

// ---------------------------------------------------------------------------
extern "C" void kernel_launch(void* const* d_in, const int* in_sizes, int n_in,
                              void* d_out, int out_size)
{
    const float* query = (const float*)d_in[0];
    const float* key   = (const float*)d_in[1];
    const float* value = (const float*)d_in[2];
    const float* Wq    = (const float*)d_in[3];
    const float* bq    = (const float*)d_in[4];
    const float* Wk    = (const float*)d_in[5];
    const float* bk    = (const float*)d_in[6];
    const float* Wv    = (const float*)d_in[7];
    const float* bv    = (const float*)d_in[8];
    float* out = (float*)d_out;

    static int attr_set = 0;
    if (!attr_set) {
        cudaFuncSetAttribute(attn_kernel, cudaFuncAttributeMaxDynamicSharedMemorySize,
                             2 * STAGE_BYTES);
        cudaFuncSetAttribute(wg_A, cudaFuncAttributeMaxDynamicSharedMemorySize,
                             TN_TOTAL);
        cudaFuncSetAttribute(wg_B, cudaFuncAttributeMaxDynamicSharedMemorySize,
                             GSM_TOTAL);
        attr_set = 1;
    }

    prep_kernel<<<1638, 256>>>(key, value, Wq, Wk, Wv, bq, bk);
    wg_A<<<272, 128, TN_TOTAL>>>(key, bq, bk);
    wg_B<<<384, 128, GSM_TOTAL>>>(bv);
    attn_kernel<<<dim3(TT / TG, BB), 256, 2 * STAGE_BYTES>>>(query, out);
}